// round 7
// baseline (speedup 1.0000x reference)
#include <cuda_runtime.h>
#include <cuda_fp16.h>
#include <math.h>

#define NELEM 8192

constexpr int TILE = 128;                 // square rank tile
constexpr int TPB  = 64;                  // threads per block (2 i's per thread, packed half2)
constexpr int NT   = NELEM / TILE;        // 64 tile rows
constexpr int NBLK = NT * (NT + 1) / 2;   // 2080 triangular rank blocks
constexpr int RCHUNKS = 16;               // dedicated reduce blocks 0..15
constexpr int RELEMS  = NELEM / RCHUNKS;  // 512 elems per chunk
constexpr int NTOT = NBLK + RCHUNKS;      // 2096 total blocks
constexpr int JCH  = 32;                  // half2 accumulation chunk (flush to fp32)

// ---------------- device scratch (statically zero-initialized; last block resets) ----
__device__ float        g_redp[RCHUNKS][19];
__device__ double       g_rank_total = 0.0;
__device__ unsigned int g_rank_count = 0u;
__device__ unsigned int g_done       = 0u;

__device__ __forceinline__ float snr_u(float s) {
    return fmaf(2.f, __expf(s * (-1.f / 15.f)), 0.5f);
}

__device__ __forceinline__ unsigned h2u(__half2 h) {
    return *reinterpret_cast<unsigned*>(&h);
}
__device__ __forceinline__ __half2 u2h(unsigned u) {
    return *reinterpret_cast<__half2*>(&u);
}

// spd_neg = -sign(td)*pd for both lanes in ONE LOP3:
// flip pd's sign bit when td's sign bit is 0:  f = pd ^ (0x8000 & ~td)  -> lut 0xD2
__device__ __forceinline__ __half2 spd_neg2(__half2 pd, __half2 td) {
    unsigned r;
    asm("lop3.b32 %0, %1, %2, 0x80008000, 0xD2;"
        : "=r"(r) : "r"(h2u(pd)), "r"(h2u(td)));
    return u2h(r);
}

__global__ __launch_bounds__(TPB) void fused_kernel(
    const float* __restrict__ pr, const float* __restrict__ tg,
    const float* __restrict__ un, const float* __restrict__ sn,
    float* __restrict__ out, int out_size)
{
    const int tid = threadIdx.x;
    const int b   = blockIdx.x;
    const unsigned full = 0xffffffffu;

    // ================= dedicated reduce blocks 0..15 (fp32, exact path) ============
    if (b < RCHUNKS) {
        float s[15];
#pragma unroll
        for (int k = 0; k < 15; ++k) s[k] = 0.f;
        float mxp = -1e30f, mxt = -1e30f, mnp = 1e30f, mnt = 1e30f;
#pragma unroll
        for (int k = 0; k < RELEMS / TPB; ++k) {
            int i = b * RELEMS + k * TPB + tid;
            float pi = pr[i], ti = tg[i], ci = un[i], si = sn[i];
            float u  = snr_u(si);
            float sm = fmaf(ti, 0.95f, 0.025f);
            float d  = pi - sm;
            s[0] += u;          s[1] += u * d * d;
            s[2] += pi;         s[3] += ti;
            s[4] += pi * pi;    s[5] += ti * ti;
            float e = fminf(fmaxf(fabsf(pi - ti), 0.001f), 1.f);
            s[6] += ci;  s[7] += ci * ci;
            s[8] += e;   s[9] += e * e;  s[10] += ci * e;
            s[11] += fmaxf(0.01f - ci, 0.f);
            s[12] += fmaxf(ci - 0.5f, 0.f);
            s[13] += fmaxf(-pi, 0.f);
            s[14] += fmaxf(pi - 1.f, 0.f);
            mxp = fmaxf(mxp, pi); mxt = fmaxf(mxt, ti);
            mnp = fminf(mnp, pi); mnt = fminf(mnt, ti);
        }
#pragma unroll
        for (int o = 16; o; o >>= 1) {
#pragma unroll
            for (int k = 0; k < 15; ++k) s[k] += __shfl_down_sync(full, s[k], o);
            mxp = fmaxf(mxp, __shfl_down_sync(full, mxp, o));
            mxt = fmaxf(mxt, __shfl_down_sync(full, mxt, o));
            mnp = fminf(mnp, __shfl_down_sync(full, mnp, o));
            mnt = fminf(mnt, __shfl_down_sync(full, mnt, o));
        }
        __shared__ float shred[TPB / 32][19];
        int wid = tid >> 5, lane = tid & 31;
        if (lane == 0) {
#pragma unroll
            for (int k = 0; k < 15; ++k) shred[wid][k] = s[k];
            shred[wid][15] = mxp; shred[wid][16] = mxt;
            shred[wid][17] = mnp; shred[wid][18] = mnt;
        }
        __syncthreads();
        if (tid == 0) {
            float a[19];
#pragma unroll
            for (int k = 0; k < 19; ++k) a[k] = shred[0][k];
#pragma unroll
            for (int w = 1; w < TPB / 32; ++w) {
#pragma unroll
                for (int k = 0; k < 15; ++k) a[k] += shred[w][k];
                a[15] = fmaxf(a[15], shred[w][15]);
                a[16] = fmaxf(a[16], shred[w][16]);
                a[17] = fminf(a[17], shred[w][17]);
                a[18] = fminf(a[18], shred[w][18]);
            }
#pragma unroll
            for (int k = 0; k < 19; ++k) g_redp[b][k] = a[k];
            __threadfence();
            atomicAdd(&g_done, 1u);   // reduce blocks never win the ticket race
        }
        return;
    }

    // ================= rank tile (packed fp16, 2 pairs/instruction) =================
    int bx = 0, rem = b - RCHUNKS, rowlen = NT;
    while (rem >= rowlen) { rem -= rowlen; --rowlen; ++bx; }
    const int by = bx + rem;
    const int i0 = bx * TILE, j0 = by * TILE;
    const bool band = (bx == by);

    __shared__ uint4 shq[TILE];           // {t2, p2, u2, pad} broadcast half2 per j
    for (int k = tid; k < TILE; k += TPB) {
        int j = j0 + k;
        shq[k] = make_uint4(h2u(__float2half2_rn(tg[j])),
                            h2u(__float2half2_rn(pr[j])),
                            h2u(__float2half2_rn(snr_u(sn[j]))), 0u);
    }
    __syncthreads();

    const int ia = i0 + tid, ib = i0 + TPB + tid;
    const float ui_a = snr_u(sn[ia]), ui_b = snr_u(sn[ib]);
    const __half2 ti2 = __halves2half2(__float2half_rn(tg[ia]), __float2half_rn(tg[ib]));
    const __half2 pi2 = __halves2half2(__float2half_rn(pr[ia]), __float2half_rn(pr[ib]));

    const __half2 C016 = __float2half2_rn(0.16f);
    const __half2 C005 = __float2half2_rn(0.05f);
    const __half2 C01  = __float2half2_rn(0.1f);
    const __half2 ZERO = __float2half2_rn(0.f);

    float aVa = 0.f, aVb = 0.f, aBa = 0.f, aBb = 0.f, aCa = 0.f, aCb = 0.f;

#define PAIR16(Q, AV, AB, AC)                                                  \
    {                                                                          \
        __half2 td2 = __hsub2(u2h((Q).x), ti2);                                \
        __half2 pd2 = __hsub2(u2h((Q).y), pi2);                                \
        __half2 sn2 = spd_neg2(pd2, td2);                                      \
        __half2 atd = __habs2(td2);                                            \
        __half2 cl  = __hmax2(atd, C01);                                       \
        __half2 v   = __hmax2(__hfma2(cl, C016, sn2), ZERO);                   \
        __half2 mk  = __hge2(atd, C005);                                       \
        __half2 vm  = __hmul2(v, mk);                                          \
        AV = __hadd2(AV, vm);                                                  \
        AB = __hfma2(u2h((Q).z), vm, AB);                                      \
        AC = __hadd2(AC, mk);                                                  \
    }

    if (!band) {
#pragma unroll
        for (int base = 0; base < TILE; base += JCH) {
            __half2 aV0 = ZERO, aB0 = ZERO, aC0 = ZERO;   // two independent chains
            __half2 aV1 = ZERO, aB1 = ZERO, aC1 = ZERO;
#pragma unroll
            for (int s = 0; s < JCH; s += 2) {
                uint4 q0 = shq[base + s];
                uint4 q1 = shq[base + s + 1];
                PAIR16(q0, aV0, aB0, aC0)
                PAIR16(q1, aV1, aB1, aC1)
            }
            float2 f;
            f = __half22float2(__hadd2(aV0, aV1)); aVa += f.x; aVb += f.y;
            f = __half22float2(__hadd2(aB0, aB1)); aBa += f.x; aBb += f.y;
            f = __half22float2(__hadd2(aC0, aC1)); aCa += f.x; aCb += f.y;
        }
    } else {
        const __half2 I2  = __halves2half2(__float2half_rn((float)tid),
                                           __float2half_rn((float)(tid + TPB)));
        const __half2 ONE = __float2half2_rn(1.f);
        __half2 jj2 = ZERO;
#pragma unroll
        for (int base = 0; base < TILE; base += JCH) {
            __half2 accV = ZERO, accB = ZERO, accC = ZERO;
#pragma unroll
            for (int s = 0; s < JCH; ++s) {
                uint4 q = shq[base + s];
                __half2 td2 = __hsub2(u2h(q.x), ti2);
                __half2 pd2 = __hsub2(u2h(q.y), pi2);
                __half2 sn2 = spd_neg2(pd2, td2);
                __half2 atd = __habs2(td2);
                __half2 cl  = __hmax2(atd, C01);
                __half2 v   = __hmax2(__hfma2(cl, C016, sn2), ZERO);
                __half2 mk  = __hmul2(__hge2(atd, C005), __hgt2(jj2, I2));
                jj2 = __hadd2(jj2, ONE);
                __half2 vm  = __hmul2(v, mk);
                accV = __hadd2(accV, vm);
                accB = __hfma2(u2h(q.z), vm, accB);
                accC = __hadd2(accC, mk);
            }
            float2 f;
            f = __half22float2(accV); aVa += f.x; aVb += f.y;
            f = __half22float2(accB); aBa += f.x; aBb += f.y;
            f = __half22float2(accC); aCa += f.x; aCb += f.y;
        }
    }
#undef PAIR16

    float tot  = fmaf(ui_a, aVa, aBa) + fmaf(ui_b, aVb, aBb);
    float cntf = aCa + aCb;               // exact integers in fp32

#pragma unroll
    for (int o = 16; o; o >>= 1) {
        tot  += __shfl_down_sync(full, tot,  o);
        cntf += __shfl_down_sync(full, cntf, o);
    }
    __shared__ float w_tot[TPB / 32];
    __shared__ float w_cnt[TPB / 32];
    int wid = tid >> 5;
    if ((tid & 31) == 0) { w_tot[wid] = tot; w_cnt[wid] = cntf; }
    __syncthreads();

    // ================= last block finalizes + resets =================
    if (tid == 0) {
        float bt = 0.f, bcf = 0.f;
#pragma unroll
        for (int w = 0; w < TPB / 32; ++w) { bt += w_tot[w]; bcf += w_cnt[w]; }
        atomicAdd(&g_rank_total, (double)bt);
        atomicAdd(&g_rank_count, (unsigned)__float2uint_rn(bcf));

        __threadfence();
        unsigned ticket = atomicAdd(&g_done, 1u);
        if (ticket == NTOT - 1) {
            __threadfence();
            const float Nf = (float)NELEM;
            float r[19];
            volatile float* vp = &g_redp[0][0];
#pragma unroll
            for (int k = 0; k < 19; ++k) r[k] = vp[k];
            for (int blk = 1; blk < RCHUNKS; ++blk) {
                volatile float* vq = &g_redp[blk][0];
#pragma unroll
                for (int k = 0; k < 15; ++k) r[k] += vq[k];
                r[15] = fmaxf(r[15], vq[15]);
                r[16] = fmaxf(r[16], vq[16]);
                r[17] = fminf(r[17], vq[17]);
                r[18] = fminf(r[18], vq[18]);
            }
            double rt = *(volatile double*)&g_rank_total;
            unsigned rc = *(volatile unsigned*)&g_rank_count;

            float m = fmaxf(r[0] / Nf, 1e-6f);
            float mse_loss = r[1] / (Nf * m);

            float rank_loss = 0.f;
            if (rc > 0) rank_loss = (float)(rt / (double)rc) * (0.5f / m);

            float mean_unc = r[6] / Nf, mean_e = r[8] / Nf;
            float mse_unc  = (r[7] - 2.f * r[10] + r[9]) / Nf;
            float cov      = r[10] / Nf - mean_unc * mean_e;
            float std_unc  = fmaxf(sqrtf(fmaxf(r[7] / Nf - mean_unc * mean_unc, 0.f)), 1e-6f);
            float std_e    = fmaxf(sqrtf(fmaxf(r[9] / Nf - mean_e * mean_e, 0.f)), 1e-6f);
            float corr     = cov / (std_unc * std_e + 1e-6f);
            float clp      = fmaxf(0.5f - corr, 0.f);
            float unc_loss = 0.5f * mse_unc + 0.3f * clp * clp
                           + 0.2f * (fmaxf(-corr, 0.f) * 10.f);

            float unc_bounds = 0.05f * ((r[11] + r[12]) / Nf);

            float mean_gap  = fabsf(r[2] / Nf - r[3] / Nf);
            float max_gap   = fmaxf(1.f - (r[15] + 1e-6f) / (r[16] + 1e-6f), 0.f);
            float prange    = r[15] - r[17], trange = r[16] - r[18];
            float range_pen = fmaxf(1.f - (prange + 1e-6f) / (trange + 1e-6f), 0.f);
            float calib = 0.2f * mean_gap + 1.5f * max_gap + 1.0f * range_pen;

            float mp = r[2] / Nf, mt = r[3] / Nf;
            float pstd = sqrtf(fmaxf(r[4] / Nf - mp * mp, 0.f));
            float tstd = sqrtf(fmaxf(r[5] / Nf - mt * mt, 0.f));
            float vr = pstd / (tstd + 1e-8f);
            float minvar = ((pstd < 0.5f * tstd) && (tstd > 1e-4f))
                         ? 2.f * fmaxf(0.5f - vr, 0.f) : 0.f;

            float bounds_pen = 5.f * ((r[13] + r[14]) / Nf);

            // bucket5: eff_rank_w = 0.6, eff_mse_w = 0.425
            float total = 0.425f * mse_loss + 0.6f * rank_loss + 0.35f * unc_loss
                        + unc_bounds + calib + minvar + bounds_pen;

            for (int k = 0; k < out_size; ++k) out[k] = total;

            // reset accumulators for next graph replay
            g_rank_total = 0.0;
            g_rank_count = 0u;
            __threadfence();
            g_done = 0u;
        }
    }
}

// ---------------- launch ----------------
extern "C" void kernel_launch(void* const* d_in, const int* in_sizes, int n_in,
                              void* d_out, int out_size) {
    const float* pr = (const float*)d_in[0];  // predictions
    const float* tg = (const float*)d_in[1];  // targets
    const float* un = (const float*)d_in[2];  // uncertainties
    const float* sn = (const float*)d_in[3];  // snr_values

    fused_kernel<<<NTOT, TPB>>>(pr, tg, un, sn, (float*)d_out, out_size);
}

// round 8
// speedup vs baseline: 1.0265x; 1.0265x over previous
#include <cuda_runtime.h>
#include <cuda_fp16.h>
#include <math.h>

#define NELEM 8192

constexpr int ITILE = 128;                // i per block (2 per thread, packed half2)
constexpr int JTILE = 64;                 // j per block
constexpr int TPB   = 64;
constexpr int NTI   = NELEM / ITILE;      // 64
constexpr int NTJ   = NELEM / JTILE;      // 128
// block rows: bi has bj in [2*bi, 128) -> rowlen = 128 - 2*bi ; total = 4160
constexpr int NBLK  = NTI * NTJ - NTI * (NTI - 1);  // 64*128 - 64*63 = 4160
constexpr int RCHUNKS = 16;               // dedicated reduce blocks 0..15
constexpr int RELEMS  = NELEM / RCHUNKS;  // 512
constexpr int NTOT = NBLK + RCHUNKS;      // 4176
constexpr int JCH  = 16;                  // half2 accumulation chunk (flush to fp32)

// ---------------- device scratch (statically zero-initialized; last block resets) ----
__device__ float        g_redp[RCHUNKS][19];
__device__ double       g_rank_total = 0.0;
__device__ unsigned int g_rank_count = 0u;
__device__ unsigned int g_done       = 0u;

__device__ __forceinline__ float snr_u(float s) {
    return fmaf(2.f, __expf(s * (-1.f / 15.f)), 0.5f);
}
__device__ __forceinline__ unsigned h2u(__half2 h) {
    return *reinterpret_cast<unsigned*>(&h);
}
__device__ __forceinline__ __half2 u2h(unsigned u) {
    return *reinterpret_cast<__half2*>(&u);
}
// spd_neg = -sign(td)*pd for both lanes in ONE LOP3 (lut 0xD2)
__device__ __forceinline__ __half2 spd_neg2(__half2 pd, __half2 td) {
    unsigned r;
    asm("lop3.b32 %0, %1, %2, 0x80008000, 0xD2;"
        : "=r"(r) : "r"(h2u(pd)), "r"(h2u(td)));
    return u2h(r);
}

__global__ __launch_bounds__(TPB) void fused_kernel(
    const float* __restrict__ pr, const float* __restrict__ tg,
    const float* __restrict__ un, const float* __restrict__ sn,
    float* __restrict__ out, int out_size)
{
    const int tid = threadIdx.x;
    const int b   = blockIdx.x;
    const unsigned full = 0xffffffffu;

    // ================= dedicated reduce blocks 0..15 (fp32, exact path) ============
    if (b < RCHUNKS) {
        float s[15];
#pragma unroll
        for (int k = 0; k < 15; ++k) s[k] = 0.f;
        float mxp = -1e30f, mxt = -1e30f, mnp = 1e30f, mnt = 1e30f;
#pragma unroll
        for (int k = 0; k < RELEMS / TPB; ++k) {
            int i = b * RELEMS + k * TPB + tid;
            float pi = pr[i], ti = tg[i], ci = un[i], si = sn[i];
            float u  = snr_u(si);
            float sm = fmaf(ti, 0.95f, 0.025f);
            float d  = pi - sm;
            s[0] += u;          s[1] += u * d * d;
            s[2] += pi;         s[3] += ti;
            s[4] += pi * pi;    s[5] += ti * ti;
            float e = fminf(fmaxf(fabsf(pi - ti), 0.001f), 1.f);
            s[6] += ci;  s[7] += ci * ci;
            s[8] += e;   s[9] += e * e;  s[10] += ci * e;
            s[11] += fmaxf(0.01f - ci, 0.f);
            s[12] += fmaxf(ci - 0.5f, 0.f);
            s[13] += fmaxf(-pi, 0.f);
            s[14] += fmaxf(pi - 1.f, 0.f);
            mxp = fmaxf(mxp, pi); mxt = fmaxf(mxt, ti);
            mnp = fminf(mnp, pi); mnt = fminf(mnt, ti);
        }
#pragma unroll
        for (int o = 16; o; o >>= 1) {
#pragma unroll
            for (int k = 0; k < 15; ++k) s[k] += __shfl_down_sync(full, s[k], o);
            mxp = fmaxf(mxp, __shfl_down_sync(full, mxp, o));
            mxt = fmaxf(mxt, __shfl_down_sync(full, mxt, o));
            mnp = fminf(mnp, __shfl_down_sync(full, mnp, o));
            mnt = fminf(mnt, __shfl_down_sync(full, mnt, o));
        }
        __shared__ float shred[TPB / 32][19];
        int wid = tid >> 5, lane = tid & 31;
        if (lane == 0) {
#pragma unroll
            for (int k = 0; k < 15; ++k) shred[wid][k] = s[k];
            shred[wid][15] = mxp; shred[wid][16] = mxt;
            shred[wid][17] = mnp; shred[wid][18] = mnt;
        }
        __syncthreads();
        if (tid == 0) {
            float a[19];
#pragma unroll
            for (int k = 0; k < 19; ++k) a[k] = shred[0][k];
#pragma unroll
            for (int w = 1; w < TPB / 32; ++w) {
#pragma unroll
                for (int k = 0; k < 15; ++k) a[k] += shred[w][k];
                a[15] = fmaxf(a[15], shred[w][15]);
                a[16] = fmaxf(a[16], shred[w][16]);
                a[17] = fminf(a[17], shred[w][17]);
                a[18] = fminf(a[18], shred[w][18]);
            }
#pragma unroll
            for (int k = 0; k < 19; ++k) g_redp[b][k] = a[k];
            __threadfence();
            atomicAdd(&g_done, 1u);   // reduce blocks never win the ticket race
        }
        return;
    }

    // ================= rank tile (i-tile 128 x j-tile 64, packed fp16) ==============
    // row bi holds bj in [2*bi, NTJ); rowlen = NTJ - 2*bi
    int bi = 0, rem = b - RCHUNKS, rowlen = NTJ;
    while (rem >= rowlen) { rem -= rowlen; rowlen -= 2; ++bi; }
    const int bj = 2 * bi + rem;
    const int i0 = bi * ITILE, j0 = bj * JTILE;
    const bool band = (rem < 2);          // rem==0 or rem==1 straddle the diagonal

    __shared__ uint4 shq[JTILE];          // {t2, p2, u2, pad} broadcast half2 per j
    {
        int j = j0 + tid;
        shq[tid] = make_uint4(h2u(__float2half2_rn(tg[j])),
                              h2u(__float2half2_rn(pr[j])),
                              h2u(__float2half2_rn(snr_u(sn[j]))), 0u);
    }
    __syncthreads();

    const int ia = i0 + tid, ib = i0 + TPB + tid;
    const float ui_a = snr_u(sn[ia]), ui_b = snr_u(sn[ib]);
    const __half2 ti2 = __halves2half2(__float2half_rn(tg[ia]), __float2half_rn(tg[ib]));
    const __half2 pi2 = __halves2half2(__float2half_rn(pr[ia]), __float2half_rn(pr[ib]));

    const __half2 C016 = __float2half2_rn(0.16f);
    const __half2 C005 = __float2half2_rn(0.05f);
    const __half2 C01  = __float2half2_rn(0.1f);
    const __half2 ZERO = __float2half2_rn(0.f);

    float aVa = 0.f, aVb = 0.f, aBa = 0.f, aBb = 0.f, aCa = 0.f, aCb = 0.f;

    if (!band) {
#pragma unroll
        for (int base = 0; base < JTILE; base += JCH) {
            __half2 accV = ZERO, accB = ZERO, accC = ZERO;
#pragma unroll
            for (int s = 0; s < JCH; ++s) {
                uint4 q = shq[base + s];
                __half2 td2 = __hsub2(u2h(q.x), ti2);
                __half2 pd2 = __hsub2(u2h(q.y), pi2);
                __half2 sn2 = spd_neg2(pd2, td2);
                __half2 atd = __habs2(td2);
                __half2 cl  = __hmax2(atd, C01);
                __half2 v   = __hmax2(__hfma2(cl, C016, sn2), ZERO);
                __half2 mk  = __hge2(atd, C005);
                __half2 vm  = __hmul2(v, mk);
                accV = __hadd2(accV, vm);
                accB = __hfma2(u2h(q.z), vm, accB);
                accC = __hadd2(accC, mk);
            }
            float2 f;
            f = __half22float2(accV); aVa += f.x; aVb += f.y;
            f = __half22float2(accB); aBa += f.x; aBb += f.y;
            f = __half22float2(accC); aCa += f.x; aCb += f.y;
        }
    } else {
        // rem==0: j0 == i0          -> lane a needs jj >  tid, lane b never passes
        // rem==1: j0 == i0 + 64     -> lane a always passes,  lane b needs jj > tid
        const __half2 I2 = (rem == 0)
            ? __halves2half2(__float2half_rn((float)tid), __float2half_rn(10000.f))
            : __halves2half2(__float2half_rn(-1.f),       __float2half_rn((float)tid));
        const __half2 ONE = __float2half2_rn(1.f);
        __half2 jj2 = ZERO;
#pragma unroll
        for (int base = 0; base < JTILE; base += JCH) {
            __half2 accV = ZERO, accB = ZERO, accC = ZERO;
#pragma unroll
            for (int s = 0; s < JCH; ++s) {
                uint4 q = shq[base + s];
                __half2 td2 = __hsub2(u2h(q.x), ti2);
                __half2 pd2 = __hsub2(u2h(q.y), pi2);
                __half2 sn2 = spd_neg2(pd2, td2);
                __half2 atd = __habs2(td2);
                __half2 cl  = __hmax2(atd, C01);
                __half2 v   = __hmax2(__hfma2(cl, C016, sn2), ZERO);
                __half2 mk  = __hmul2(__hge2(atd, C005), __hgt2(jj2, I2));
                jj2 = __hadd2(jj2, ONE);
                __half2 vm  = __hmul2(v, mk);
                accV = __hadd2(accV, vm);
                accB = __hfma2(u2h(q.z), vm, accB);
                accC = __hadd2(accC, mk);
            }
            float2 f;
            f = __half22float2(accV); aVa += f.x; aVb += f.y;
            f = __half22float2(accB); aBa += f.x; aBb += f.y;
            f = __half22float2(accC); aCa += f.x; aCb += f.y;
        }
    }

    float tot  = fmaf(ui_a, aVa, aBa) + fmaf(ui_b, aVb, aBb);
    float cntf = aCa + aCb;               // exact integers in fp32

#pragma unroll
    for (int o = 16; o; o >>= 1) {
        tot  += __shfl_down_sync(full, tot,  o);
        cntf += __shfl_down_sync(full, cntf, o);
    }
    __shared__ float w_tot[TPB / 32];
    __shared__ float w_cnt[TPB / 32];
    int wid = tid >> 5;
    if ((tid & 31) == 0) { w_tot[wid] = tot; w_cnt[wid] = cntf; }
    __syncthreads();

    // ================= last block finalizes + resets =================
    if (tid == 0) {
        float bt = 0.f, bcf = 0.f;
#pragma unroll
        for (int w = 0; w < TPB / 32; ++w) { bt += w_tot[w]; bcf += w_cnt[w]; }
        atomicAdd(&g_rank_total, (double)bt);
        atomicAdd(&g_rank_count, (unsigned)__float2uint_rn(bcf));

        __threadfence();
        unsigned ticket = atomicAdd(&g_done, 1u);
        if (ticket == NTOT - 1) {
            __threadfence();
            const float Nf = (float)NELEM;
            float r[19];
            volatile float* vp = &g_redp[0][0];
#pragma unroll
            for (int k = 0; k < 19; ++k) r[k] = vp[k];
            for (int blk = 1; blk < RCHUNKS; ++blk) {
                volatile float* vq = &g_redp[blk][0];
#pragma unroll
                for (int k = 0; k < 15; ++k) r[k] += vq[k];
                r[15] = fmaxf(r[15], vq[15]);
                r[16] = fmaxf(r[16], vq[16]);
                r[17] = fminf(r[17], vq[17]);
                r[18] = fminf(r[18], vq[18]);
            }
            double rt = *(volatile double*)&g_rank_total;
            unsigned rc = *(volatile unsigned*)&g_rank_count;

            float m = fmaxf(r[0] / Nf, 1e-6f);
            float mse_loss = r[1] / (Nf * m);

            float rank_loss = 0.f;
            if (rc > 0) rank_loss = (float)(rt / (double)rc) * (0.5f / m);

            float mean_unc = r[6] / Nf, mean_e = r[8] / Nf;
            float mse_unc  = (r[7] - 2.f * r[10] + r[9]) / Nf;
            float cov      = r[10] / Nf - mean_unc * mean_e;
            float std_unc  = fmaxf(sqrtf(fmaxf(r[7] / Nf - mean_unc * mean_unc, 0.f)), 1e-6f);
            float std_e    = fmaxf(sqrtf(fmaxf(r[9] / Nf - mean_e * mean_e, 0.f)), 1e-6f);
            float corr     = cov / (std_unc * std_e + 1e-6f);
            float clp      = fmaxf(0.5f - corr, 0.f);
            float unc_loss = 0.5f * mse_unc + 0.3f * clp * clp
                           + 0.2f * (fmaxf(-corr, 0.f) * 10.f);

            float unc_bounds = 0.05f * ((r[11] + r[12]) / Nf);

            float mean_gap  = fabsf(r[2] / Nf - r[3] / Nf);
            float max_gap   = fmaxf(1.f - (r[15] + 1e-6f) / (r[16] + 1e-6f), 0.f);
            float prange    = r[15] - r[17], trange = r[16] - r[18];
            float range_pen = fmaxf(1.f - (prange + 1e-6f) / (trange + 1e-6f), 0.f);
            float calib = 0.2f * mean_gap + 1.5f * max_gap + 1.0f * range_pen;

            float mp = r[2] / Nf, mt = r[3] / Nf;
            float pstd = sqrtf(fmaxf(r[4] / Nf - mp * mp, 0.f));
            float tstd = sqrtf(fmaxf(r[5] / Nf - mt * mt, 0.f));
            float vr = pstd / (tstd + 1e-8f);
            float minvar = ((pstd < 0.5f * tstd) && (tstd > 1e-4f))
                         ? 2.f * fmaxf(0.5f - vr, 0.f) : 0.f;

            float bounds_pen = 5.f * ((r[13] + r[14]) / Nf);

            // bucket5: eff_rank_w = 0.6, eff_mse_w = 0.425
            float total = 0.425f * mse_loss + 0.6f * rank_loss + 0.35f * unc_loss
                        + unc_bounds + calib + minvar + bounds_pen;

            for (int k = 0; k < out_size; ++k) out[k] = total;

            // reset accumulators for next graph replay
            g_rank_total = 0.0;
            g_rank_count = 0u;
            __threadfence();
            g_done = 0u;
        }
    }
}

// ---------------- launch ----------------
extern "C" void kernel_launch(void* const* d_in, const int* in_sizes, int n_in,
                              void* d_out, int out_size) {
    const float* pr = (const float*)d_in[0];  // predictions
    const float* tg = (const float*)d_in[1];  // targets
    const float* un = (const float*)d_in[2];  // uncertainties
    const float* sn = (const float*)d_in[3];  // snr_values

    fused_kernel<<<NTOT, TPB>>>(pr, tg, un, sn, (float*)d_out, out_size);
}

// round 9
// speedup vs baseline: 1.1198x; 1.0909x over previous
#include <cuda_runtime.h>
#include <cuda_fp16.h>
#include <math.h>

#define NELEM 8192

constexpr int ITILE = 128;                // i per block (2 per thread, packed half2)
constexpr int JTILE = 64;                 // j per block
constexpr int TPB   = 64;
constexpr int NTI   = NELEM / ITILE;      // 64
constexpr int NTJ   = NELEM / JTILE;      // 128
constexpr int NBLK  = NTI * NTJ - NTI * (NTI - 1);  // 4160
constexpr int RCHUNKS = 16;               // dedicated reduce blocks 0..15
constexpr int RELEMS  = NELEM / RCHUNKS;  // 512
constexpr int NTOT = NBLK + RCHUNKS;      // 4176
constexpr int JCH  = 16;                  // half2 accumulation chunk (flush to fp32)

// ---------------- device scratch (statically zero-initialized; last block resets) ----
__device__ float        g_redp[RCHUNKS][19];
__device__ double       g_rank_total = 0.0;
__device__ unsigned int g_rank_count = 0u;
__device__ unsigned int g_done       = 0u;

__device__ __forceinline__ float snr_u(float s) {
    return fmaf(2.f, __expf(s * (-1.f / 15.f)), 0.5f);
}
__device__ __forceinline__ unsigned h2u(__half2 h) {
    return *reinterpret_cast<unsigned*>(&h);
}
__device__ __forceinline__ __half2 u2h(unsigned u) {
    return *reinterpret_cast<__half2*>(&u);
}
// spd_neg = -sign(td)*pd for both lanes in ONE LOP3 (lut 0xD2)
__device__ __forceinline__ __half2 spd_neg2(__half2 pd, __half2 td) {
    unsigned r;
    asm("lop3.b32 %0, %1, %2, 0x80008000, 0xD2;"
        : "=r"(r) : "r"(h2u(pd)), "r"(h2u(td)));
    return u2h(r);
}
// abs via single LOP3 (clear sign bits)
__device__ __forceinline__ __half2 habs2i(__half2 a) {
    unsigned r;
    asm("and.b32 %0, %1, 0x7FFF7FFF;" : "=r"(r) : "r"(h2u(a)));
    return u2h(r);
}
// force single-instruction packed ops
__device__ __forceinline__ __half2 hmax2i(__half2 a, __half2 b) {
    unsigned r;
    asm("max.f16x2 %0, %1, %2;" : "=r"(r) : "r"(h2u(a)), "r"(h2u(b)));
    return u2h(r);
}
__device__ __forceinline__ __half2 hfma2_relu(__half2 a, __half2 b, __half2 c) {
    unsigned r;
    asm("fma.rn.relu.f16x2 %0, %1, %2, %3;"
        : "=r"(r) : "r"(h2u(a)), "r"(h2u(b)), "r"(h2u(c)));
    return u2h(r);
}
__device__ __forceinline__ __half2 hge2i(__half2 a, __half2 b) {   // 1.0/0.0 per lane
    unsigned r;
    asm("set.ge.f16x2.f16x2 %0, %1, %2;" : "=r"(r) : "r"(h2u(a)), "r"(h2u(b)));
    return u2h(r);
}
__device__ __forceinline__ __half2 hgt2i(__half2 a, __half2 b) {
    unsigned r;
    asm("set.gt.f16x2.f16x2 %0, %1, %2;" : "=r"(r) : "r"(h2u(a)), "r"(h2u(b)));
    return u2h(r);
}

__global__ __launch_bounds__(TPB) void fused_kernel(
    const float* __restrict__ pr, const float* __restrict__ tg,
    const float* __restrict__ un, const float* __restrict__ sn,
    float* __restrict__ out, int out_size)
{
    const int tid = threadIdx.x;
    const int b   = blockIdx.x;
    const unsigned full = 0xffffffffu;

    // ================= dedicated reduce blocks 0..15 (fp32, exact path) ============
    if (b < RCHUNKS) {
        float s[15];
#pragma unroll
        for (int k = 0; k < 15; ++k) s[k] = 0.f;
        float mxp = -1e30f, mxt = -1e30f, mnp = 1e30f, mnt = 1e30f;
#pragma unroll
        for (int k = 0; k < RELEMS / TPB; ++k) {
            int i = b * RELEMS + k * TPB + tid;
            float pi = pr[i], ti = tg[i], ci = un[i], si = sn[i];
            float u  = snr_u(si);
            float sm = fmaf(ti, 0.95f, 0.025f);
            float d  = pi - sm;
            s[0] += u;          s[1] += u * d * d;
            s[2] += pi;         s[3] += ti;
            s[4] += pi * pi;    s[5] += ti * ti;
            float e = fminf(fmaxf(fabsf(pi - ti), 0.001f), 1.f);
            s[6] += ci;  s[7] += ci * ci;
            s[8] += e;   s[9] += e * e;  s[10] += ci * e;
            s[11] += fmaxf(0.01f - ci, 0.f);
            s[12] += fmaxf(ci - 0.5f, 0.f);
            s[13] += fmaxf(-pi, 0.f);
            s[14] += fmaxf(pi - 1.f, 0.f);
            mxp = fmaxf(mxp, pi); mxt = fmaxf(mxt, ti);
            mnp = fminf(mnp, pi); mnt = fminf(mnt, ti);
        }
#pragma unroll
        for (int o = 16; o; o >>= 1) {
#pragma unroll
            for (int k = 0; k < 15; ++k) s[k] += __shfl_down_sync(full, s[k], o);
            mxp = fmaxf(mxp, __shfl_down_sync(full, mxp, o));
            mxt = fmaxf(mxt, __shfl_down_sync(full, mxt, o));
            mnp = fminf(mnp, __shfl_down_sync(full, mnp, o));
            mnt = fminf(mnt, __shfl_down_sync(full, mnt, o));
        }
        __shared__ float shred[TPB / 32][19];
        int wid = tid >> 5, lane = tid & 31;
        if (lane == 0) {
#pragma unroll
            for (int k = 0; k < 15; ++k) shred[wid][k] = s[k];
            shred[wid][15] = mxp; shred[wid][16] = mxt;
            shred[wid][17] = mnp; shred[wid][18] = mnt;
        }
        __syncthreads();
        if (tid == 0) {
            float a[19];
#pragma unroll
            for (int k = 0; k < 19; ++k) a[k] = shred[0][k];
#pragma unroll
            for (int w = 1; w < TPB / 32; ++w) {
#pragma unroll
                for (int k = 0; k < 15; ++k) a[k] += shred[w][k];
                a[15] = fmaxf(a[15], shred[w][15]);
                a[16] = fmaxf(a[16], shred[w][16]);
                a[17] = fminf(a[17], shred[w][17]);
                a[18] = fminf(a[18], shred[w][18]);
            }
#pragma unroll
            for (int k = 0; k < 19; ++k) g_redp[b][k] = a[k];
            __threadfence();
            atomicAdd(&g_done, 1u);   // reduce blocks never win the ticket race
        }
        return;
    }

    // ================= rank tile (i-tile 128 x j-tile 64, packed fp16) ==============
    int bi = 0, rem = b - RCHUNKS, rowlen = NTJ;
    while (rem >= rowlen) { rem -= rowlen; rowlen -= 2; ++bi; }
    const int bj = 2 * bi + rem;
    const int i0 = bi * ITILE, j0 = bj * JTILE;
    const bool band = (rem < 2);          // rem==0 or rem==1 straddle the diagonal

    __shared__ uint4 shq[JTILE];          // {t2, p2, u2, pad} broadcast half2 per j
    {
        int j = j0 + tid;
        shq[tid] = make_uint4(h2u(__float2half2_rn(tg[j])),
                              h2u(__float2half2_rn(pr[j])),
                              h2u(__float2half2_rn(snr_u(sn[j]))), 0u);
    }
    __syncthreads();

    const int ia = i0 + tid, ib = i0 + TPB + tid;
    const float ui_a = snr_u(sn[ia]), ui_b = snr_u(sn[ib]);
    const __half2 ti2 = __halves2half2(__float2half_rn(tg[ia]), __float2half_rn(tg[ib]));
    const __half2 pi2 = __halves2half2(__float2half_rn(pr[ia]), __float2half_rn(pr[ib]));

    const __half2 C016 = __float2half2_rn(0.16f);
    const __half2 C005 = __float2half2_rn(0.05f);
    const __half2 C01  = __float2half2_rn(0.1f);
    const __half2 ZERO = __float2half2_rn(0.f);

    float aVa = 0.f, aVb = 0.f, aBa = 0.f, aBb = 0.f, aCa = 0.f, aCb = 0.f;

    if (!band) {
#pragma unroll
        for (int base = 0; base < JTILE; base += JCH) {
            __half2 accV = ZERO, accB = ZERO, accC = ZERO;
#pragma unroll
            for (int s = 0; s < JCH; ++s) {
                uint4 q = shq[base + s];
                __half2 td2 = __hsub2(u2h(q.x), ti2);
                __half2 pd2 = __hsub2(u2h(q.y), pi2);
                __half2 sn2 = spd_neg2(pd2, td2);
                __half2 atd = habs2i(td2);
                __half2 cl  = hmax2i(atd, C01);
                __half2 v   = hfma2_relu(cl, C016, sn2);   // fused hinge
                __half2 mk  = hge2i(atd, C005);
                __half2 vm  = __hmul2(v, mk);
                accV = __hadd2(accV, vm);
                accB = __hfma2(u2h(q.z), vm, accB);
                accC = __hadd2(accC, mk);
            }
            float2 f;
            f = __half22float2(accV); aVa += f.x; aVb += f.y;
            f = __half22float2(accB); aBa += f.x; aBb += f.y;
            f = __half22float2(accC); aCa += f.x; aCb += f.y;
        }
    } else {
        // rem==0: j0 == i0      -> lane a needs jj >  tid, lane b never passes
        // rem==1: j0 == i0 + 64 -> lane a always passes,  lane b needs jj > tid
        const __half2 I2 = (rem == 0)
            ? __halves2half2(__float2half_rn((float)tid), __float2half_rn(10000.f))
            : __halves2half2(__float2half_rn(-1.f),       __float2half_rn((float)tid));
        const __half2 ONE = __float2half2_rn(1.f);
        __half2 jj2 = ZERO;
#pragma unroll
        for (int base = 0; base < JTILE; base += JCH) {
            __half2 accV = ZERO, accB = ZERO, accC = ZERO;
#pragma unroll
            for (int s = 0; s < JCH; ++s) {
                uint4 q = shq[base + s];
                __half2 td2 = __hsub2(u2h(q.x), ti2);
                __half2 pd2 = __hsub2(u2h(q.y), pi2);
                __half2 sn2 = spd_neg2(pd2, td2);
                __half2 atd = habs2i(td2);
                __half2 cl  = hmax2i(atd, C01);
                __half2 v   = hfma2_relu(cl, C016, sn2);
                __half2 mk  = __hmul2(hge2i(atd, C005), hgt2i(jj2, I2));
                jj2 = __hadd2(jj2, ONE);
                __half2 vm  = __hmul2(v, mk);
                accV = __hadd2(accV, vm);
                accB = __hfma2(u2h(q.z), vm, accB);
                accC = __hadd2(accC, mk);
            }
            float2 f;
            f = __half22float2(accV); aVa += f.x; aVb += f.y;
            f = __half22float2(accB); aBa += f.x; aBb += f.y;
            f = __half22float2(accC); aCa += f.x; aCb += f.y;
        }
    }

    float tot  = fmaf(ui_a, aVa, aBa) + fmaf(ui_b, aVb, aBb);
    float cntf = aCa + aCb;               // exact integers in fp32

#pragma unroll
    for (int o = 16; o; o >>= 1) {
        tot  += __shfl_down_sync(full, tot,  o);
        cntf += __shfl_down_sync(full, cntf, o);
    }
    __shared__ float w_tot[TPB / 32];
    __shared__ float w_cnt[TPB / 32];
    int wid = tid >> 5;
    if ((tid & 31) == 0) { w_tot[wid] = tot; w_cnt[wid] = cntf; }
    __syncthreads();

    // ================= last block finalizes + resets =================
    if (tid == 0) {
        float bt = 0.f, bcf = 0.f;
#pragma unroll
        for (int w = 0; w < TPB / 32; ++w) { bt += w_tot[w]; bcf += w_cnt[w]; }
        atomicAdd(&g_rank_total, (double)bt);
        atomicAdd(&g_rank_count, (unsigned)__float2uint_rn(bcf));

        __threadfence();
        unsigned ticket = atomicAdd(&g_done, 1u);
        if (ticket == NTOT - 1) {
            __threadfence();
            const float Nf = (float)NELEM;
            float r[19];
            volatile float* vp = &g_redp[0][0];
#pragma unroll
            for (int k = 0; k < 19; ++k) r[k] = vp[k];
            for (int blk = 1; blk < RCHUNKS; ++blk) {
                volatile float* vq = &g_redp[blk][0];
#pragma unroll
                for (int k = 0; k < 15; ++k) r[k] += vq[k];
                r[15] = fmaxf(r[15], vq[15]);
                r[16] = fmaxf(r[16], vq[16]);
                r[17] = fminf(r[17], vq[17]);
                r[18] = fminf(r[18], vq[18]);
            }
            double rt = *(volatile double*)&g_rank_total;
            unsigned rc = *(volatile unsigned*)&g_rank_count;

            float m = fmaxf(r[0] / Nf, 1e-6f);
            float mse_loss = r[1] / (Nf * m);

            float rank_loss = 0.f;
            if (rc > 0) rank_loss = (float)(rt / (double)rc) * (0.5f / m);

            float mean_unc = r[6] / Nf, mean_e = r[8] / Nf;
            float mse_unc  = (r[7] - 2.f * r[10] + r[9]) / Nf;
            float cov      = r[10] / Nf - mean_unc * mean_e;
            float std_unc  = fmaxf(sqrtf(fmaxf(r[7] / Nf - mean_unc * mean_unc, 0.f)), 1e-6f);
            float std_e    = fmaxf(sqrtf(fmaxf(r[9] / Nf - mean_e * mean_e, 0.f)), 1e-6f);
            float corr     = cov / (std_unc * std_e + 1e-6f);
            float clp      = fmaxf(0.5f - corr, 0.f);
            float unc_loss = 0.5f * mse_unc + 0.3f * clp * clp
                           + 0.2f * (fmaxf(-corr, 0.f) * 10.f);

            float unc_bounds = 0.05f * ((r[11] + r[12]) / Nf);

            float mean_gap  = fabsf(r[2] / Nf - r[3] / Nf);
            float max_gap   = fmaxf(1.f - (r[15] + 1e-6f) / (r[16] + 1e-6f), 0.f);
            float prange    = r[15] - r[17], trange = r[16] - r[18];
            float range_pen = fmaxf(1.f - (prange + 1e-6f) / (trange + 1e-6f), 0.f);
            float calib = 0.2f * mean_gap + 1.5f * max_gap + 1.0f * range_pen;

            float mp = r[2] / Nf, mt = r[3] / Nf;
            float pstd = sqrtf(fmaxf(r[4] / Nf - mp * mp, 0.f));
            float tstd = sqrtf(fmaxf(r[5] / Nf - mt * mt, 0.f));
            float vr = pstd / (tstd + 1e-8f);
            float minvar = ((pstd < 0.5f * tstd) && (tstd > 1e-4f))
                         ? 2.f * fmaxf(0.5f - vr, 0.f) : 0.f;

            float bounds_pen = 5.f * ((r[13] + r[14]) / Nf);

            // bucket5: eff_rank_w = 0.6, eff_mse_w = 0.425
            float total = 0.425f * mse_loss + 0.6f * rank_loss + 0.35f * unc_loss
                        + unc_bounds + calib + minvar + bounds_pen;

            for (int k = 0; k < out_size; ++k) out[k] = total;

            // reset accumulators for next graph replay
            g_rank_total = 0.0;
            g_rank_count = 0u;
            __threadfence();
            g_done = 0u;
        }
    }
}

// ---------------- launch ----------------
extern "C" void kernel_launch(void* const* d_in, const int* in_sizes, int n_in,
                              void* d_out, int out_size) {
    const float* pr = (const float*)d_in[0];  // predictions
    const float* tg = (const float*)d_in[1];  // targets
    const float* un = (const float*)d_in[2];  // uncertainties
    const float* sn = (const float*)d_in[3];  // snr_values

    fused_kernel<<<NTOT, TPB>>>(pr, tg, un, sn, (float*)d_out, out_size);
}